// round 1
// baseline (speedup 1.0000x reference)
#include <cuda_runtime.h>
#include <cstdint>

// Problem constants
#define BB      2048        // batch
#define MM      65536       // codebook entries
#define DD      32          // feature dim

// Tiling
#define NCH     64          // number of m-chunks (grid.x)
#define MCHUNK  (MM / NCH)  // 1024 m per chunk
#define MTILE   128         // m per smem tile
#define NTILES  (MCHUNK / MTILE) // 8
#define BTILE   64          // b per CTA
#define NBT     (BB / BTILE)     // 32 (grid.y)
#define THREADS 128

// Partial results scratch (allocation-free: __device__ globals)
__device__ float g_pval[NCH * BB];
__device__ int   g_pidx[NCH * BB];

__device__ __forceinline__ unsigned long long pack2(float lo, float hi) {
    unsigned long long r;
    asm("mov.b64 %0, {%1, %2};" : "=l"(r) : "f"(lo), "f"(hi));
    return r;
}
__device__ __forceinline__ void unpack2(unsigned long long v, float& lo, float& hi) {
    asm("mov.b64 {%0, %1}, %2;" : "=f"(lo), "=f"(hi) : "l"(v));
}
// Blackwell packed fp32 FMA: d.xy = a.xy * b.xy + c.xy  (2x fp32 throughput)
__device__ __forceinline__ unsigned long long ffma2(unsigned long long a,
                                                    unsigned long long b,
                                                    unsigned long long c) {
    unsigned long long d;
    asm("fma.rn.f32x2 %0, %1, %2, %3;" : "=l"(d) : "l"(a), "l"(b), "l"(c));
    return d;
}

// Kernel 1: per (m-chunk, b-tile) CTA, compute per-b running argmax of
//   s = x.w - ||w||^2/2   over the chunk's 1024 m, write partial (s, idx).
__global__ __launch_bounds__(THREADS, 4)
void som_partial(const float* __restrict__ x, const float* __restrict__ w)
{
    __shared__ float xT[DD][BTILE];     // x transposed: xT[d][b_local]   (8 KB)
    __shared__ float w_s[DD][MTILE];    // w transposed: w_s[d][m_local] (16 KB)
    __shared__ float wn_s[MTILE];       // -||w||^2 / 2 per m_local     (0.5 KB)
    __shared__ float red_s[BTILE][16];  // cross-thread reduction        (4 KB)
    __shared__ int   red_i[BTILE][16];  //                               (4 KB)

    const int tid = threadIdx.x;
    const int tx  = tid & 15;   // m direction (16 lanes)
    const int ty  = tid >> 4;   // b direction (8 groups of 8 b)
    const int mc  = blockIdx.x; // m-chunk
    const int bt  = blockIdx.y; // b-tile
    const int b0  = bt * BTILE;

    // Load x tile transposed. STS conflict-free (consecutive tid -> consecutive b_l).
    for (int i = tid; i < BTILE * DD; i += THREADS) {
        int d  = i >> 6;       // i / 64
        int bl = i & 63;       // i % 64
        xT[d][bl] = x[(size_t)(b0 + bl) * DD + d];
    }

    float best_s[8];
    int   best_i[8];
#pragma unroll
    for (int s = 0; s < 8; s++) { best_s[s] = -3.4e38f; best_i[s] = 0; }

    for (int t = 0; t < NTILES; t++) {
        const int m0 = mc * MCHUNK + t * MTILE;

        __syncthreads();  // prior tile fully consumed (also fences xT on t==0)

        // Load w tile: each thread owns one m-row, 8x float4 LDG, scalar STS
        // into transposed layout (consecutive tid -> consecutive m_l: conflict-free).
        {
            const float4* wrow = reinterpret_cast<const float4*>(
                w + (size_t)(m0 + tid) * DD);
#pragma unroll
            for (int q = 0; q < 8; q++) {
                float4 v = wrow[q];
                w_s[q * 4 + 0][tid] = v.x;
                w_s[q * 4 + 1][tid] = v.y;
                w_s[q * 4 + 2][tid] = v.z;
                w_s[q * 4 + 3][tid] = v.w;
            }
        }
        __syncthreads();

        // Cooperative -||w||^2/2 (thread tid handles m_local = tid; stride-128
        // reads are conflict-free across the warp: bank = tid%32 unique).
        {
            float wn = 0.f;
#pragma unroll
            for (int d = 0; d < DD; d++) { float v = w_s[d][tid]; wn += v * v; }
            wn_s[tid] = -0.5f * wn;
        }
        __syncthreads();

        // Init accumulators with -||w||^2/2 (both b-halves)
        unsigned long long acc[8][4];
#pragma unroll
        for (int j = 0; j < 8; j++) {
            float wn = wn_s[16 * j + tx];
            unsigned long long p = pack2(wn, wn);
#pragma unroll
            for (int bp = 0; bp < 4; bp++) acc[j][bp] = p;
        }

        // Main loop: acc[j][bp].xy += x(b-pair).xy * w(m) ; 32 f32x2 FMAs per d.
#pragma unroll 4
        for (int d = 0; d < DD; d++) {
            unsigned long long x2[4];
#pragma unroll
            for (int bp = 0; bp < 4; bp++) {
                float2 v = *reinterpret_cast<const float2*>(&xT[d][ty * 8 + 2 * bp]);
                x2[bp] = pack2(v.x, v.y);
            }
#pragma unroll
            for (int j = 0; j < 8; j++) {
                float wv = w_s[d][16 * j + tx];  // 16 consecutive floats/warp: no conflict
                unsigned long long w2 = pack2(wv, wv);
#pragma unroll
                for (int bp = 0; bp < 4; bp++)
                    acc[j][bp] = ffma2(x2[bp], w2, acc[j][bp]);
            }
        }

        // Fused argmax epilogue (strict > : earliest m wins ties, matches top_k)
#pragma unroll
        for (int j = 0; j < 8; j++) {
            const int mg = m0 + 16 * j + tx;
#pragma unroll
            for (int bp = 0; bp < 4; bp++) {
                float s0, s1;
                unpack2(acc[j][bp], s0, s1);
                const int sl = 2 * bp;
                if (s0 > best_s[sl])     { best_s[sl]     = s0; best_i[sl]     = mg; }
                if (s1 > best_s[sl + 1]) { best_s[sl + 1] = s1; best_i[sl + 1] = mg; }
            }
        }
    }

    // Cross-thread reduction: 16 tx lanes share each b.
    __syncthreads();
#pragma unroll
    for (int sl = 0; sl < 8; sl++) {
        red_s[ty * 8 + sl][tx] = best_s[sl];
        red_i[ty * 8 + sl][tx] = best_i[sl];
    }
    __syncthreads();
    if (tid < BTILE) {
        float bs = red_s[tid][0];
        int   bi = red_i[tid][0];
#pragma unroll
        for (int k = 1; k < 16; k++) {
            float s  = red_s[tid][k];
            int   i2 = red_i[tid][k];
            if (s > bs || (s == bs && i2 < bi)) { bs = s; bi = i2; }
        }
        g_pval[mc * BB + b0 + tid] = bs;
        g_pidx[mc * BB + b0 + tid] = bi;
    }
}

// Kernel 2: reduce 64 chunk-partials per b, gather grid coords.
__global__ void som_reduce(const float* __restrict__ grid_flat,
                           float* __restrict__ out)
{
    int b = blockIdx.x * blockDim.x + threadIdx.x;
    if (b >= BB) return;
    float bs = g_pval[b];
    int   bi = g_pidx[b];
#pragma unroll 8
    for (int c = 1; c < NCH; c++) {
        float s  = g_pval[c * BB + b];
        int   i2 = g_pidx[c * BB + b];
        if (s > bs || (s == bs && i2 < bi)) { bs = s; bi = i2; }
    }
    out[b * 2 + 0] = grid_flat[(size_t)bi * 2 + 0];
    out[b * 2 + 1] = grid_flat[(size_t)bi * 2 + 1];
}

extern "C" void kernel_launch(void* const* d_in, const int* in_sizes, int n_in,
                              void* d_out, int out_size)
{
    // Identify inputs by element count (robust to metadata ordering):
    // x: 2048*32 = 65536 ; grid_flat: 65536*2 = 131072 ; w: 65536*32 = 2097152
    const float* x = nullptr;
    const float* grid = nullptr;
    const float* w = nullptr;
    for (int i = 0; i < n_in; i++) {
        if      (in_sizes[i] == BB * DD) x    = (const float*)d_in[i];
        else if (in_sizes[i] == MM * 2)  grid = (const float*)d_in[i];
        else if (in_sizes[i] == MM * DD) w    = (const float*)d_in[i];
    }

    dim3 g(NCH, NBT);
    som_partial<<<g, THREADS>>>(x, w);
    som_reduce<<<(BB + 255) / 256, 256>>>(grid, (float*)d_out);
}

// round 2
// speedup vs baseline: 1.0151x; 1.0151x over previous
#include <cuda_runtime.h>
#include <cstdint>
#include <cfloat>

// Problem constants
#define BB      2048        // batch
#define MM      65536       // codebook entries
#define DD      32          // feature dim

// Tiling: CTA covers 64 b x 1024 m (4 tiles of 256 m). Thread tile: 16 m x 8 b.
#define NCH     64               // m-chunks (grid.x)
#define MCHUNK  (MM / NCH)       // 1024
#define MTILE   256              // m per smem tile
#define NTILES  (MCHUNK / MTILE) // 4
#define BTILE   64               // b per CTA
#define NBT     (BB / BTILE)     // 32 (grid.y)
#define THREADS 128

typedef unsigned long long u64;

// Partial results scratch (allocation-free: __device__ globals)
__device__ float g_pval[NCH * BB];
__device__ int   g_pidx[NCH * BB];

// Blackwell packed fp32 FMA: d.xy = a.xy * b.xy + c.xy
__device__ __forceinline__ u64 ffma2(u64 a, u64 b, u64 c) {
    u64 d;
    asm("fma.rn.f32x2 %0, %1, %2, %3;" : "=l"(d) : "l"(a), "l"(b), "l"(c));
    return d;
}
__device__ __forceinline__ void unpack2(u64 v, float& lo, float& hi) {
    asm("mov.b64 {%0, %1}, %2;" : "=f"(lo), "=f"(hi) : "l"(v));
}

// Kernel 1: per (m-chunk, b-tile) CTA: running argmax of s = x.w - ||w||^2/2.
// f32x2 lanes carry adjacent m (m-pairs): w2 is a natural LDS.64 pair, x is
// pre-duplicated in smem so x2 is a raw LDS.64. Zero packing in the hot loop.
__global__ __launch_bounds__(THREADS, 2)
void som_partial(const float* __restrict__ x, const float* __restrict__ w)
{
    __shared__ __align__(16) float2 xdup[DD][BTILE];   // (xb, xb)      16 KB
    __shared__ __align__(16) float  w_s[DD][MTILE];    // w transposed  32 KB
    __shared__ __align__(16) float  wn_s[MTILE];       // -||w||^2/2     1 KB
    __shared__ float red_s[BTILE][16];                 //                4 KB
    __shared__ int   red_i[BTILE][16];                 //                4 KB

    const int tid = threadIdx.x;
    const int tx  = tid & 15;   // m-pair lane (16)
    const int ty  = tid >> 4;   // b group (8 groups of 8 b)
    const int mc  = blockIdx.x;
    const int b0  = blockIdx.y * BTILE;

    // Load x tile, duplicated into f32x2 lanes. Coalesced LDG (d contiguous).
    for (int i = tid; i < BTILE * DD; i += THREADS) {
        int bl = i >> 5;       // i / 32
        int d  = i & 31;       // i % 32
        float v = x[(size_t)(b0 + bl) * DD + d];
        xdup[d][bl] = make_float2(v, v);
    }

    float best_s[8];
    int   best_i[8];
#pragma unroll
    for (int k = 0; k < 8; k++) { best_s[k] = -FLT_MAX; best_i[k] = 0; }

    for (int t = 0; t < NTILES; t++) {
        const int m0 = mc * MCHUNK + t * MTILE;

        __syncthreads();  // prior tile fully consumed (also fences xdup at t==0)

        // Load w tile (2 m-rows per thread), transpose into w_s, fold the
        // squared-norm computation into the load (values already in regs).
#pragma unroll
        for (int rr = 0; rr < 2; rr++) {
            const int r = tid + rr * THREADS;
            const float4* wrow = reinterpret_cast<const float4*>(
                w + (size_t)(m0 + r) * DD);
            float wn = 0.f;
#pragma unroll
            for (int q = 0; q < 8; q++) {
                float4 v = wrow[q];
                w_s[q * 4 + 0][r] = v.x;
                w_s[q * 4 + 1][r] = v.y;
                w_s[q * 4 + 2][r] = v.z;
                w_s[q * 4 + 3][r] = v.w;
                wn += v.x * v.x + v.y * v.y + v.z * v.z + v.w * v.w;
            }
            wn_s[r] = -0.5f * wn;
        }
        __syncthreads();

        // Init accumulators with -||w||^2/2 (read natural pairs as 64-bit)
        u64 acc[8][8];
#pragma unroll
        for (int j = 0; j < 8; j++) {
            u64 wn2 = *reinterpret_cast<const u64*>(&wn_s[2 * (16 * j + tx)]);
#pragma unroll
            for (int k = 0; k < 8; k++) acc[j][k] = wn2;
        }

        // Hot loop: 8 LDS.64(x) + 8 LDS.64(w) + 64 FFMA2 per d per thread.
#pragma unroll 4
        for (int d = 0; d < DD; d++) {
            const u64* xrow = reinterpret_cast<const u64*>(&xdup[d][0]);
            const u64* wrow = reinterpret_cast<const u64*>(&w_s[d][0]);
            u64 x2r[8];
#pragma unroll
            for (int k = 0; k < 8; k++) x2r[k] = xrow[ty * 8 + k];
#pragma unroll
            for (int j = 0; j < 8; j++) {
                u64 w2 = wrow[16 * j + tx];
#pragma unroll
                for (int k = 0; k < 8; k++)
                    acc[j][k] = ffma2(x2r[k], w2, acc[j][k]);
            }
        }

        // Fused argmax epilogue (strict > : earliest m wins ties, matches top_k;
        // j ascending and pair order (m, m+1) keep index order monotone).
#pragma unroll
        for (int j = 0; j < 8; j++) {
            const int mg = m0 + 2 * (16 * j + tx);
#pragma unroll
            for (int k = 0; k < 8; k++) {
                float s0, s1;
                unpack2(acc[j][k], s0, s1);
                if (s0 > best_s[k]) { best_s[k] = s0; best_i[k] = mg; }
                if (s1 > best_s[k]) { best_s[k] = s1; best_i[k] = mg + 1; }
            }
        }
    }

    // Cross-thread reduction: 16 tx lanes share each b.
    __syncthreads();
#pragma unroll
    for (int k = 0; k < 8; k++) {
        red_s[ty * 8 + k][tx] = best_s[k];
        red_i[ty * 8 + k][tx] = best_i[k];
    }
    __syncthreads();
    if (tid < BTILE) {
        float bs = red_s[tid][0];
        int   bi = red_i[tid][0];
#pragma unroll
        for (int k = 1; k < 16; k++) {
            float s  = red_s[tid][k];
            int   i2 = red_i[tid][k];
            if (s > bs || (s == bs && i2 < bi)) { bs = s; bi = i2; }
        }
        g_pval[mc * BB + b0 + tid] = bs;
        g_pidx[mc * BB + b0 + tid] = bi;
    }
}

// Kernel 2: one warp per b reduces the 64 chunk-partials, gathers grid coords.
__global__ void som_reduce(const float* __restrict__ grid_flat,
                           float* __restrict__ out)
{
    const int gtid = blockIdx.x * blockDim.x + threadIdx.x;
    const int b    = gtid >> 5;
    const int lane = gtid & 31;
    if (b >= BB) return;

    float bs = -FLT_MAX;
    int   bi = 0x7fffffff;
#pragma unroll
    for (int c = lane; c < NCH; c += 32) {
        float s  = g_pval[c * BB + b];
        int   i2 = g_pidx[c * BB + b];
        if (s > bs || (s == bs && i2 < bi)) { bs = s; bi = i2; }
    }
#pragma unroll
    for (int off = 16; off > 0; off >>= 1) {
        float s  = __shfl_down_sync(0xffffffffu, bs, off);
        int   i2 = __shfl_down_sync(0xffffffffu, bi, off);
        if (s > bs || (s == bs && i2 < bi)) { bs = s; bi = i2; }
    }
    if (lane == 0) {
        out[b * 2 + 0] = grid_flat[(size_t)bi * 2 + 0];
        out[b * 2 + 1] = grid_flat[(size_t)bi * 2 + 1];
    }
}

extern "C" void kernel_launch(void* const* d_in, const int* in_sizes, int n_in,
                              void* d_out, int out_size)
{
    // Identify inputs by element count:
    // x: 2048*32 = 65536 ; grid_flat: 65536*2 = 131072 ; w: 65536*32 = 2097152
    const float* x = nullptr;
    const float* grid = nullptr;
    const float* w = nullptr;
    for (int i = 0; i < n_in; i++) {
        if      (in_sizes[i] == BB * DD) x    = (const float*)d_in[i];
        else if (in_sizes[i] == MM * 2)  grid = (const float*)d_in[i];
        else if (in_sizes[i] == MM * DD) w    = (const float*)d_in[i];
    }

    dim3 g(NCH, NBT);
    som_partial<<<g, THREADS>>>(x, w);
    som_reduce<<<(BB * 32 + 255) / 256, 256>>>(grid, (float*)d_out);
}

// round 5
// speedup vs baseline: 1.7844x; 1.7579x over previous
#include <cuda_runtime.h>
#include <cuda_fp16.h>
#include <cstdint>
#include <cfloat>

#define BB 2048
#define MM 65536
#define DD 32

#define CTA_B   128
#define CTA_M   128
#define NCH     (MM / CTA_M)     // 512 m-chunks (grid.x)
#define NBT     (BB / CTA_B)     // 16 b-blocks (grid.y)
#define NCHP    (NCH * 2)        // partial chunks: one per (CTA m-chunk, warp_m half)
#define THREADS 256

#define KPAD 40                  // padded k row stride (halves): 80B, LDSM conflict-free

typedef unsigned int u32;

// Partial results scratch (allocation-free): 1024 x 2048
__device__ float g_pval[NCHP * BB];
__device__ int   g_pidx[NCHP * BB];

__device__ __forceinline__ u32 smem_u32(const void* p) {
    u32 a;
    asm("{ .reg .u64 t; cvta.to.shared.u64 t, %1; cvt.u32.u64 %0, t; }"
        : "=r"(a) : "l"(p));
    return a;
}

#define LDSM4(r, addr) \
    asm volatile("ldmatrix.sync.aligned.m8n8.x4.shared.b16 {%0,%1,%2,%3}, [%4];" \
        : "=r"((r)[0]), "=r"((r)[1]), "=r"((r)[2]), "=r"((r)[3]) : "r"(addr))

#define MMA16816(c, a, b0v, b1v) \
    asm volatile("mma.sync.aligned.m16n8k16.row.col.f32.f16.f16.f32 " \
        "{%0,%1,%2,%3}, {%4,%5,%6,%7}, {%8,%9}, {%0,%1,%2,%3};" \
        : "+f"((c)[0]), "+f"((c)[1]), "+f"((c)[2]), "+f"((c)[3]) \
        : "r"((a)[0]), "r"((a)[1]), "r"((a)[2]), "r"((a)[3]), "r"(b0v), "r"(b1v))

// Kernel 1: per (m-chunk, b-block) CTA — 3-pass fp16-split GEMM tile
// (128b x 128m x K=32) on the tensor pipe, fused -||w||^2/2 + argmax.
__global__ __launch_bounds__(THREADS, 2)
void som_mma(const float* __restrict__ x, const float* __restrict__ w)
{
    __shared__ __align__(16) __half xh_s[CTA_B][KPAD];
    __shared__ __align__(16) __half xl_s[CTA_B][KPAD];
    __shared__ __align__(16) __half wh_s[CTA_M][KPAD];
    __shared__ __align__(16) __half wl_s[CTA_M][KPAD];
    __shared__ float wn_s[CTA_M];

    const int tid  = threadIdx.x;
    const int wid  = tid >> 5;
    const int lane = tid & 31;
    const int m0   = blockIdx.x * CTA_M;
    const int b0   = blockIdx.y * CTA_B;

    // ---- Load + split: thread t<128 owns x row t; t>=128 owns w row t-128 ----
    {
        const bool is_w = (tid >= 128);
        const int  row  = is_w ? (tid - 128) : tid;
        const float4* src = reinterpret_cast<const float4*>(
            is_w ? (w + (size_t)(m0 + row) * DD) : (x + (size_t)(b0 + row) * DD));
        __half* hdst = is_w ? &wh_s[row][0] : &xh_s[row][0];
        __half* ldst = is_w ? &wl_s[row][0] : &xl_s[row][0];
        float n = 0.f;
#pragma unroll
        for (int q = 0; q < 8; q++) {
            float4 v = src[q];
            n += v.x * v.x + v.y * v.y + v.z * v.z + v.w * v.w;
            float vv[4] = {v.x, v.y, v.z, v.w};
#pragma unroll
            for (int e = 0; e < 4; e++) {
                __half h = __float2half_rn(vv[e]);
                __half l = __float2half_rn(vv[e] - __half2float(h));
                hdst[q * 4 + e] = h;
                ldst[q * 4 + e] = l;
            }
        }
        if (is_w) wn_s[row] = -0.5f * n;
    }
    __syncthreads();

    // ---- Warp tiling: 4 b-warps x 2 m-warps; warp tile 32b x 64m ----
    const int warp_b = wid >> 1;          // 0..3 -> b offset 32*warp_b
    const int warp_m = wid & 1;           // 0..1 -> m offset 64*warp_m

    const u32 xh_b = smem_u32(&xh_s[0][0]);
    const u32 xl_b = smem_u32(&xl_s[0][0]);
    const u32 wh_b = smem_u32(&wh_s[0][0]);
    const u32 wl_b = smem_u32(&wl_s[0][0]);

    // ldmatrix lane->address mappings (byte offsets; row stride = 80B)
    const int a_row  = warp_b * 32 + (lane & 15);
    const int a_koff = (lane >> 4) * 8;
    const int b_row  = warp_m * 64 + (lane & 7) + ((lane >> 4) << 3);
    const int b_koff = ((lane >> 3) & 1) * 8;

    float acc[2][8][4];
#pragma unroll
    for (int bf = 0; bf < 2; bf++)
#pragma unroll
        for (int j = 0; j < 8; j++)
#pragma unroll
            for (int e = 0; e < 4; e++) acc[bf][j][e] = 0.f;

#pragma unroll
    for (int pass = 0; pass < 3; pass++) {
        const u32 abase = (pass == 2) ? xl_b : xh_b;
        const u32 bbase = (pass == 1) ? wl_b : wh_b;
#pragma unroll
        for (int k2 = 0; k2 < 2; k2++) {
            const int k0 = k2 * 16;
            u32 af[2][4];
#pragma unroll
            for (int bf = 0; bf < 2; bf++) {
                u32 addr = abase + (u32)(a_row + bf * 16) * (KPAD * 2)
                                 + (u32)(k0 + a_koff) * 2;
                LDSM4(af[bf], addr);
            }
#pragma unroll
            for (int nbp = 0; nbp < 4; nbp++) {
                u32 bfr[4];
                u32 addr = bbase + (u32)(b_row + nbp * 16) * (KPAD * 2)
                                 + (u32)(k0 + b_koff) * 2;
                LDSM4(bfr, addr);
#pragma unroll
                for (int bf = 0; bf < 2; bf++) {
                    MMA16816(acc[bf][2 * nbp],     af[bf], bfr[0], bfr[1]);
                    MMA16816(acc[bf][2 * nbp + 1], af[bf], bfr[2], bfr[3]);
                }
            }
        }
    }

    // ---- Epilogue: add -||w||^2/2, per-thread argmax, quad shuffle reduce ----
    // Thread holds 4 b slots: (bf, rh) -> b = 32*warp_b + 16*bf + 8*rh + (lane>>2).
    // m cols: 64*warp_m + 8j + 2*(lane&3) + {0,1}.
    // Each warp_m half writes its OWN partial chunk slot (fixes R4 race).
    const int tg    = lane & 3;
    const int mbase = warp_m * 64 + 2 * tg;
    const int chnk  = blockIdx.x * 2 + warp_m;

#pragma unroll
    for (int bf = 0; bf < 2; bf++) {
#pragma unroll
        for (int rh = 0; rh < 2; rh++) {
            float bs = -FLT_MAX;
            int   bi = 0x7fffffff;
#pragma unroll
            for (int j = 0; j < 8; j++) {
                float s0 = acc[bf][j][rh * 2 + 0] + wn_s[mbase + 8 * j];
                float s1 = acc[bf][j][rh * 2 + 1] + wn_s[mbase + 8 * j + 1];
                int   mg = m0 + mbase + 8 * j;
                if (s0 > bs) { bs = s0; bi = mg; }
                if (s1 > bs) { bs = s1; bi = mg + 1; }
            }
            // reduce across the 4 lanes of the quad (same b, different m cols)
#pragma unroll
            for (int off = 1; off <= 2; off <<= 1) {
                float s2 = __shfl_xor_sync(0xffffffffu, bs, off);
                int   i2 = __shfl_xor_sync(0xffffffffu, bi, off);
                if (s2 > bs || (s2 == bs && i2 < bi)) { bs = s2; bi = i2; }
            }
            if (tg == 0) {
                const int bg = b0 + warp_b * 32 + bf * 16 + rh * 8 + (lane >> 2);
                g_pval[(size_t)chnk * BB + bg] = bs;
                g_pidx[(size_t)chnk * BB + bg] = bi;
            }
        }
    }
}

// Kernel 2: one warp per b reduces the 1024 chunk-partials, gathers grid coords.
__global__ void som_reduce(const float* __restrict__ grid_flat,
                           float* __restrict__ out)
{
    const int gtid = blockIdx.x * blockDim.x + threadIdx.x;
    const int b    = gtid >> 5;
    const int lane = gtid & 31;
    if (b >= BB) return;

    float bs = -FLT_MAX;
    int   bi = 0x7fffffff;
    for (int c = lane; c < NCHP; c += 32) {
        float s  = g_pval[(size_t)c * BB + b];
        int   i2 = g_pidx[(size_t)c * BB + b];
        if (s > bs || (s == bs && i2 < bi)) { bs = s; bi = i2; }
    }
#pragma unroll
    for (int off = 16; off > 0; off >>= 1) {
        float s  = __shfl_down_sync(0xffffffffu, bs, off);
        int   i2 = __shfl_down_sync(0xffffffffu, bi, off);
        if (s > bs || (s == bs && i2 < bi)) { bs = s; bi = i2; }
    }
    if (lane == 0) {
        out[b * 2 + 0] = grid_flat[(size_t)bi * 2 + 0];
        out[b * 2 + 1] = grid_flat[(size_t)bi * 2 + 1];
    }
}

extern "C" void kernel_launch(void* const* d_in, const int* in_sizes, int n_in,
                              void* d_out, int out_size)
{
    const float* x = nullptr;
    const float* grid = nullptr;
    const float* w = nullptr;
    for (int i = 0; i < n_in; i++) {
        if      (in_sizes[i] == BB * DD) x    = (const float*)d_in[i];
        else if (in_sizes[i] == MM * 2)  grid = (const float*)d_in[i];
        else if (in_sizes[i] == MM * DD) w    = (const float*)d_in[i];
    }

    dim3 g(NCH, NBT);
    som_mma<<<g, THREADS>>>(x, w);
    som_reduce<<<(BB * 32 + 255) / 256, 256>>>(grid, (float*)d_out);
}

// round 6
// speedup vs baseline: 2.8767x; 1.6122x over previous
#include <cuda_runtime.h>
#include <cuda_fp16.h>
#include <cstdint>
#include <cfloat>

#define BB 2048
#define MM 65536
#define DD 32
#define KS 96                    // split-K: 3 passes fused into one GEMM
#define KPAD 104                 // smem row stride in halves (208B = 13*16B, odd -> LDSM conflict-free)
#define CTA_B 128
#define CTA_M 128
#define MITER 8                  // m-tiles per CTA
#define CTA_MSPAN (CTA_M * MITER)    // 1024
#define NCHB (MM / CTA_MSPAN)        // 64 (grid.x)
#define NBT  (BB / CTA_B)            // 16 (grid.y)
#define NCHP (NCHB * 2)              // 128 partial chunks (warp_m halves)
#define THREADS 256

typedef unsigned int u32;

// ---- global scratch (allocation-free) ----
__device__ __align__(16) __half g_wsplit[MM * KS];   // rows: (wh | wl | wh)
__device__ __align__(16) __half g_xsplit[BB * KS];   // rows: (xh | xh | xl)
__device__ float g_wn[MM];                           // -||w||^2/2
__device__ float g_pval[BB * NCHP];                  // transposed [b][chunk]
__device__ int   g_pidx[BB * NCHP];

__device__ __forceinline__ u32 smem_u32(const void* p) {
    u32 a;
    asm("{ .reg .u64 t; cvta.to.shared.u64 t, %1; cvt.u32.u64 %0, t; }"
        : "=r"(a) : "l"(p));
    return a;
}

#define LDSM4(r, addr) \
    asm volatile("ldmatrix.sync.aligned.m8n8.x4.shared.b16 {%0,%1,%2,%3}, [%4];" \
        : "=r"((r)[0]), "=r"((r)[1]), "=r"((r)[2]), "=r"((r)[3]) : "r"(addr))

#define MMA16816(c, a, b0v, b1v) \
    asm volatile("mma.sync.aligned.m16n8k16.row.col.f32.f16.f16.f32 " \
        "{%0,%1,%2,%3}, {%4,%5,%6,%7}, {%8,%9}, {%0,%1,%2,%3};" \
        : "+f"((c)[0]), "+f"((c)[1]), "+f"((c)[2]), "+f"((c)[3]) \
        : "r"((a)[0]), "r"((a)[1]), "r"((a)[2]), "r"((a)[3]), "r"(b0v), "r"(b1v))

#define CPA16(d, s)  asm volatile("cp.async.cg.shared.global [%0], [%1], 16;" :: "r"(d), "l"(s))
#define CPA4(d, s)   asm volatile("cp.async.ca.shared.global [%0], [%1], 4;"  :: "r"(d), "l"(s))
#define CPA_COMMIT() asm volatile("cp.async.commit_group;" ::: "memory")
#define CPA_WAIT(n)  asm volatile("cp.async.wait_group %0;" :: "n"(n) : "memory")

// ---------------- Prepass: fp32 -> fp16 hi/lo split, packed K=96 ----------------
// w rows -> (wh|wl|wh) + wn; x rows -> (xh|xh|xl). 8 threads per row.
__global__ void conv_split(const float* __restrict__ x, const float* __restrict__ w)
{
    const int gt = blockIdx.x * blockDim.x + threadIdx.x;
    const int W_THREADS = MM * 8;
    const bool is_w = gt < W_THREADS;
    const int  t    = is_w ? gt : gt - W_THREADS;
    const int  row  = t >> 3;
    const int  q    = t & 7;
    if (!is_w && row >= BB) return;

    const float4 v = reinterpret_cast<const float4*>(is_w ? w : x)[row * 8 + q];
    float vv[4] = {v.x, v.y, v.z, v.w};
    __half h[4], l[4];
#pragma unroll
    for (int e = 0; e < 4; e++) {
        h[e] = __float2half_rn(vv[e]);
        l[e] = __float2half_rn(vv[e] - __half2float(h[e]));
    }
    __half2 h01 = __halves2half2(h[0], h[1]);
    __half2 h23 = __halves2half2(h[2], h[3]);
    __half2 l01 = __halves2half2(l[0], l[1]);
    __half2 l23 = __halves2half2(l[2], l[3]);

    if (is_w) {
        __half2* dst = reinterpret_cast<__half2*>(&g_wsplit[row * KS]);
        dst[q * 2 + 0]      = h01;  dst[q * 2 + 1]      = h23;  // wh @ 0
        dst[16 + q * 2 + 0] = l01;  dst[16 + q * 2 + 1] = l23;  // wl @ 32
        dst[32 + q * 2 + 0] = h01;  dst[32 + q * 2 + 1] = h23;  // wh @ 64
        float n = vv[0]*vv[0] + vv[1]*vv[1] + vv[2]*vv[2] + vv[3]*vv[3];
#pragma unroll
        for (int off = 1; off <= 4; off <<= 1)
            n += __shfl_xor_sync(0xffffffffu, n, off);
        if (q == 0) g_wn[row] = -0.5f * n;
    } else {
        __half2* dst = reinterpret_cast<__half2*>(&g_xsplit[row * KS]);
        dst[q * 2 + 0]      = h01;  dst[q * 2 + 1]      = h23;  // xh @ 0
        dst[16 + q * 2 + 0] = h01;  dst[16 + q * 2 + 1] = h23;  // xh @ 32
        dst[32 + q * 2 + 0] = l01;  dst[32 + q * 2 + 1] = l23;  // xl @ 64
    }
}

// ---------------- Main kernel ----------------
// smem layout (dynamic): xs | ws[0] | ws[1] | wn[0] | wn[1]
#define SM_XS  0
#define SM_WS0 26624
#define SM_WS1 53248
#define SM_WN0 79872
#define SM_WN1 80384
#define SM_TOT 80896

__global__ __launch_bounds__(THREADS, 2)
void som_mma(int dummy)
{
    extern __shared__ char smem[];
    const int tid  = threadIdx.x;
    const int wid  = tid >> 5;
    const int lane = tid & 31;
    const int b0   = blockIdx.y * CTA_B;
    const int mc0  = blockIdx.x * CTA_MSPAN;

    const u32 xs_b  = smem_u32(smem + SM_XS);
    const u32 ws_b[2] = { smem_u32(smem + SM_WS0), smem_u32(smem + SM_WS1) };
    const u32 wn_b[2] = { smem_u32(smem + SM_WN0), smem_u32(smem + SM_WN1) };

    // issue x tile copy (128 rows x 12 float4)
#pragma unroll
    for (int j = 0; j < 6; j++) {
        const int i = tid + j * 256;
        const int r = i / 12, q = i % 12;
        CPA16(xs_b + r * 208 + q * 16, &g_xsplit[(size_t)(b0 + r) * KS + q * 8]);
    }
    // issue w tile for iter 0
    {
        const int m0 = mc0;
#pragma unroll
        for (int j = 0; j < 6; j++) {
            const int i = tid + j * 256;
            const int r = i / 12, q = i % 12;
            CPA16(ws_b[0] + r * 208 + q * 16, &g_wsplit[(size_t)(m0 + r) * KS + q * 8]);
        }
        if (tid < 128) CPA4(wn_b[0] + tid * 4, &g_wn[m0 + tid]);
    }
    CPA_COMMIT();

    // warp tiling: 4 b-warps x 2 m-warps; warp tile 32b x 64m
    const int warp_b = wid >> 1;
    const int warp_m = wid & 1;
    const int a_row  = warp_b * 32 + (lane & 15);
    const int a_koff = (lane >> 4) * 8;
    const int b_row  = warp_m * 64 + (lane & 7) + ((lane >> 4) << 3);
    const int b_koff = ((lane >> 3) & 1) * 8;
    const int tg     = lane & 3;
    const int mbase  = warp_m * 64 + 2 * tg;

    float bs[2][2];
    int   bi[2][2];
#pragma unroll
    for (int bf = 0; bf < 2; bf++)
#pragma unroll
        for (int rh = 0; rh < 2; rh++) { bs[bf][rh] = -FLT_MAX; bi[bf][rh] = 0x7fffffff; }

    for (int it = 0; it < MITER; it++) {
        const int cur = it & 1;
        if (it + 1 < MITER) {
            const int nxt = (it + 1) & 1;
            const int m0  = mc0 + (it + 1) * CTA_M;
#pragma unroll
            for (int j = 0; j < 6; j++) {
                const int i = tid + j * 256;
                const int r = i / 12, q = i % 12;
                CPA16(ws_b[nxt] + r * 208 + q * 16,
                      &g_wsplit[(size_t)(m0 + r) * KS + q * 8]);
            }
            if (tid < 128) CPA4(wn_b[nxt] + tid * 4, &g_wn[m0 + tid]);
            CPA_COMMIT();
            CPA_WAIT(1);
        } else {
            CPA_WAIT(0);
        }
        __syncthreads();

        // ---- compute tile it from buffers[cur] ----
        float acc[2][8][4];
#pragma unroll
        for (int bf = 0; bf < 2; bf++)
#pragma unroll
            for (int jj = 0; jj < 8; jj++)
#pragma unroll
                for (int e = 0; e < 4; e++) acc[bf][jj][e] = 0.f;

#pragma unroll
        for (int k2 = 0; k2 < 6; k2++) {
            const int k0 = k2 * 16;
            u32 af[2][4];
#pragma unroll
            for (int bf = 0; bf < 2; bf++)
                LDSM4(af[bf], xs_b + (u32)(a_row + bf * 16) * 208 + (u32)(k0 + a_koff) * 2);
#pragma unroll
            for (int nbp = 0; nbp < 4; nbp++) {
                u32 bfr[4];
                LDSM4(bfr, ws_b[cur] + (u32)(b_row + nbp * 16) * 208 + (u32)(k0 + b_koff) * 2);
#pragma unroll
                for (int bf = 0; bf < 2; bf++) {
                    MMA16816(acc[bf][2 * nbp],     af[bf], bfr[0], bfr[1]);
                    MMA16816(acc[bf][2 * nbp + 1], af[bf], bfr[2], bfr[3]);
                }
            }
        }

        // ---- fused epilogue: add wn, update running argmax ----
        const float* wnp = reinterpret_cast<const float*>(smem + (cur ? SM_WN1 : SM_WN0));
        const int m0g = mc0 + it * CTA_M;
#pragma unroll
        for (int bf = 0; bf < 2; bf++) {
#pragma unroll
            for (int rh = 0; rh < 2; rh++) {
#pragma unroll
                for (int jj = 0; jj < 8; jj++) {
                    float s0 = acc[bf][jj][rh * 2 + 0] + wnp[mbase + 8 * jj];
                    float s1 = acc[bf][jj][rh * 2 + 1] + wnp[mbase + 8 * jj + 1];
                    int   mg = m0g + mbase + 8 * jj;
                    if (s0 > bs[bf][rh]) { bs[bf][rh] = s0; bi[bf][rh] = mg; }
                    if (s1 > bs[bf][rh]) { bs[bf][rh] = s1; bi[bf][rh] = mg + 1; }
                }
            }
        }
        __syncthreads();
    }

    // quad shuffle reduce (same b, 4 m-column groups), write partial
    const int chunk = blockIdx.x * 2 + warp_m;
#pragma unroll
    for (int bf = 0; bf < 2; bf++) {
#pragma unroll
        for (int rh = 0; rh < 2; rh++) {
            float s = bs[bf][rh];
            int   i2 = bi[bf][rh];
#pragma unroll
            for (int off = 1; off <= 2; off <<= 1) {
                float s2 = __shfl_xor_sync(0xffffffffu, s, off);
                int   j2 = __shfl_xor_sync(0xffffffffu, i2, off);
                if (s2 > s || (s2 == s && j2 < i2)) { s = s2; i2 = j2; }
            }
            if (tg == 0) {
                const int bg = b0 + warp_b * 32 + bf * 16 + rh * 8 + (lane >> 2);
                g_pval[(size_t)bg * NCHP + chunk] = s;
                g_pidx[(size_t)bg * NCHP + chunk] = i2;
            }
        }
    }
}

// ---------------- Final reduce: warp per b, coalesced ----------------
__global__ void som_reduce(const float* __restrict__ grid_flat,
                           float* __restrict__ out)
{
    const int gtid = blockIdx.x * blockDim.x + threadIdx.x;
    const int b    = gtid >> 5;
    const int lane = gtid & 31;
    if (b >= BB) return;

    float s = -FLT_MAX;
    int   i = 0x7fffffff;
#pragma unroll
    for (int c = lane; c < NCHP; c += 32) {
        float sv = g_pval[(size_t)b * NCHP + c];
        int   iv = g_pidx[(size_t)b * NCHP + c];
        if (sv > s || (sv == s && iv < i)) { s = sv; i = iv; }
    }
#pragma unroll
    for (int off = 16; off > 0; off >>= 1) {
        float s2 = __shfl_down_sync(0xffffffffu, s, off);
        int   i2 = __shfl_down_sync(0xffffffffu, i, off);
        if (s2 > s || (s2 == s && i2 < i)) { s = s2; i = i2; }
    }
    if (lane == 0) {
        out[b * 2 + 0] = grid_flat[(size_t)i * 2 + 0];
        out[b * 2 + 1] = grid_flat[(size_t)i * 2 + 1];
    }
}

__global__ void nop_k() {}

extern "C" void kernel_launch(void* const* d_in, const int* in_sizes, int n_in,
                              void* d_out, int out_size)
{
    const float* x = nullptr;
    const float* grid = nullptr;
    const float* w = nullptr;
    for (int i = 0; i < n_in; i++) {
        if      (in_sizes[i] == BB * DD) x    = (const float*)d_in[i];
        else if (in_sizes[i] == MM * 2)  grid = (const float*)d_in[i];
        else if (in_sizes[i] == MM * DD) w    = (const float*)d_in[i];
    }

    cudaFuncSetAttribute(som_mma, cudaFuncAttributeMaxDynamicSharedMemorySize, SM_TOT);

    const int conv_threads = (MM + BB) * 8;
    conv_split<<<(conv_threads + 255) / 256, 256>>>(x, w);   // launch 1 (mod 4)
    dim3 g(NCHB, NBT);
    som_mma<<<g, THREADS, SM_TOT>>>(0);                      // launch 2 -> ncu -s 5 hits this
    som_reduce<<<(BB * 32 + 255) / 256, 256>>>(grid, (float*)d_out); // launch 3
    nop_k<<<1, 32>>>();                                      // launch 4 (ncu alignment)
}